// round 14
// baseline (speedup 1.0000x reference)
#include <cuda_runtime.h>
#include <cuda_fp16.h>
#include <cstdint>
#include <math.h>

#define BATCH 8
#define SEQ   2048
#define DIM   512
#define MROWS (BATCH*SEQ)   // 16384

// ===========================================================================
// Scratch in __device__ globals (allocation-free rule)
// ===========================================================================
__device__ __align__(256) __half g_xh[(size_t)MROWS * DIM];
__device__ __align__(256) __half g_wh[3][DIM * DIM];
__device__ __align__(256) __half g_qh[(size_t)MROWS * DIM];
__device__ __align__(256) __half g_kh[(size_t)MROWS * DIM];
__device__ __align__(256) __half g_vth[(size_t)BATCH * DIM * SEQ];  // V^T [b][d][k], scaled in place by 1/z
__device__ __align__(256) __half g_ph[(size_t)BATCH * SEQ * SEQ];   // exp(S)
__device__ __align__(256) float  g_zpart[(size_t)BATCH * 16 * SEQ]; // col-sum partials

// ===========================================================================
// PTX helpers (base ISA: cp.async / ldmatrix / mma.sync fp16)
// ===========================================================================
__device__ __forceinline__ uint32_t smem_u32(const void* p) {
    uint32_t a;
    asm("{ .reg .u64 t; cvta.to.shared.u64 t, %1; cvt.u32.u64 %0, t; }" : "=r"(a) : "l"(p));
    return a;
}
__device__ __forceinline__ void cp16(uint32_t s, const void* g) {
    asm volatile("cp.async.cg.shared.global [%0], [%1], 16;" :: "r"(s), "l"(g) : "memory");
}
#define CP_COMMIT()  asm volatile("cp.async.commit_group;" ::: "memory")
#define CP_WAIT3()   asm volatile("cp.async.wait_group 3;" ::: "memory")

#define LDSM4(r0, r1, r2, r3, addr) \
    asm volatile("ldmatrix.sync.aligned.m8n8.x4.shared.b16 {%0,%1,%2,%3}, [%4];" \
                 : "=r"(r0), "=r"(r1), "=r"(r2), "=r"(r3) : "r"(addr))

#define MMA_FP16(c, a, b) \
    asm volatile("mma.sync.aligned.m16n8k16.row.col.f32.f16.f16.f32 " \
                 "{%0,%1,%2,%3}, {%4,%5,%6,%7}, {%8,%9}, {%0,%1,%2,%3};" \
                 : "+f"((c)[0]), "+f"((c)[1]), "+f"((c)[2]), "+f"((c)[3]) \
                 : "r"((a)[0]), "r"((a)[1]), "r"((a)[2]), "r"((a)[3]), \
                   "r"((b)[0]), "r"((b)[1]))

// SMEM tile geometry: 128 rows x 32 fp16 (64B), padded to 80B/row (conflict-free)
#define ROW_B       80
#define TILE_B      (128 * ROW_B)          // 10240
#define STAGE_B     (2 * TILE_B)           // 20480 (A, B)
#define NSTAGE      5
#define DYN_SMEM    (NSTAGE * STAGE_B)     // 102400

#define NTHREADS    128                    // 4 warps, 2M x 2N, warp tile 64x64

__device__ __forceinline__ uint32_t pack_h2(float a, float b) {
    __half2 h = __floats2half2_rn(a, b);
    return *(uint32_t*)&h;
}

// ===========================================================================
// cp.async one K-chunk (32 cols) of A and B tiles into a stage.
// 512 x 16B per tile; each of 128 threads does 4 per tile.
// ===========================================================================
__device__ __forceinline__ void issue_chunk(
    uint32_t sbase, const char* a, const char* b,
    int ldaB, int ldbB, int koff, int tid)
{
    #pragma unroll
    for (int i = 0; i < 4; i++) {
        const int c = tid + (i << 7);
        const int r = c >> 2;
        const int sg = (c & 3) << 4;
        const uint32_t so = (uint32_t)(r * ROW_B + sg);
        cp16(sbase + so,          a + (size_t)r * (size_t)ldaB + koff + sg);
        cp16(sbase + TILE_B + so, b + (size_t)r * (size_t)ldbB + koff + sg);
    }
}

// ===========================================================================
// Compute one K-chunk (32), single-pass fp16, warp tile 64M x 64N.
// Per warp per chunk: 8 LDSM4 + 64 MMA (was 6 + 32 with 32x64 tiles);
// total CTA smem reads drop 48KB -> 32KB per chunk.
// ===========================================================================
__device__ __forceinline__ void compute_chunk(
    uint32_t sbase, int warpM, int warpN, int lane, float acc[4][8][4])
{
    const int rsel = (lane & 7) + ((lane >> 3) & 1) * 8;
    const int ksel = (lane >> 4) * 8;
    #pragma unroll
    for (int ks = 0; ks < 2; ks++) {
        const int kb = (ks * 16 + ksel) * 2;   // bytes
        uint32_t a_r[4][4];
        #pragma unroll
        for (int m = 0; m < 4; m++) {
            const uint32_t ad = sbase + (uint32_t)((warpM * 64 + m * 16 + rsel) * ROW_B + kb);
            LDSM4(a_r[m][0], a_r[m][1], a_r[m][2], a_r[m][3], ad);
        }
        uint32_t b_r[8][2];
        #pragma unroll
        for (int np = 0; np < 4; np++) {
            const uint32_t bd = sbase + TILE_B +
                (uint32_t)((warpN * 64 + np * 16 + rsel) * ROW_B + kb);
            uint32_t r0, r1, r2, r3;
            LDSM4(r0, r1, r2, r3, bd);
            b_r[2*np][0] = r0; b_r[2*np+1][0] = r1; b_r[2*np][1] = r2; b_r[2*np+1][1] = r3;
        }
        #pragma unroll
        for (int m = 0; m < 4; m++)
            #pragma unroll
            for (int n = 0; n < 8; n++)
                MMA_FP16(acc[m][n], a_r[m], b_r[n]);
    }
}

// ===========================================================================
// Full CTA GEMM core (128x128 tile, 128 threads, 4 warps 2Mx2N, 1-pass fp16)
// Single-__syncthreads mainloop (proven structure):
//   per iter: wait(NSTAGE-2) -> sync -> issue chunk c+NSTAGE-1 -> compute(c)
// ===========================================================================
__device__ __forceinline__ void gemm_mma_core(
    const __half* a, int lda, const __half* b, int ldb,
    int K, char* dsm, float acc[4][8][4])
{
    const int tid = threadIdx.x;
    const int lane = tid & 31;
    const int wid = tid >> 5;
    const int warpM = wid >> 1;
    const int warpN = wid & 1;
    const uint32_t sdyn = smem_u32(dsm);
    const int ldaB = lda * 2, ldbB = ldb * 2;
    const int NC = K / 32;

    #pragma unroll
    for (int m = 0; m < 4; m++)
        #pragma unroll
        for (int n = 0; n < 8; n++)
            #pragma unroll
            for (int q = 0; q < 4; q++) acc[m][n][q] = 0.0f;

    #pragma unroll
    for (int p = 0; p < NSTAGE - 1; p++) {
        issue_chunk(sdyn + (uint32_t)p * STAGE_B,
                    (const char*)a, (const char*)b, ldaB, ldbB, p * 64, tid);
        CP_COMMIT();
    }
    for (int c = 0; c < NC; c++) {
        CP_WAIT3();                       // chunk c landed (3 newest groups may pend)
        __syncthreads();                  // visibility + slot-overwrite protection
        const int cn = c + NSTAGE - 1;
        if (cn < NC)
            issue_chunk(sdyn + (uint32_t)(cn % NSTAGE) * STAGE_B,
                        (const char*)a, (const char*)b, ldaB, ldbB, cn * 64, tid);
        CP_COMMIT();
        compute_chunk(sdyn + (uint32_t)(c % NSTAGE) * STAGE_B, warpM, warpN, lane, acc);
    }
    __syncthreads();   // all warps done computing before epilogue reuses dsm
}

// Per-warp smem patch: 64 rows x 68 floats (padded)
#define PATCH_B 17408
__device__ __forceinline__ float* acc_to_patch(char* dsm, int wid, int lane,
                                               float acc[4][8][4])
{
    float* patch = (float*)(dsm + wid * PATCH_B);
    const int r = lane >> 2;
    const int q2 = (lane & 3) * 2;
    #pragma unroll
    for (int m = 0; m < 4; m++)
        #pragma unroll
        for (int n = 0; n < 8; n++) {
            const int cb = n * 8 + q2;
            patch[(m*16 + r)     * 68 + cb]     = acc[m][n][0];
            patch[(m*16 + r)     * 68 + cb + 1] = acc[m][n][1];
            patch[(m*16 + r + 8) * 68 + cb]     = acc[m][n][2];
            patch[(m*16 + r + 8) * 68 + cb + 1] = acc[m][n][3];
        }
    __syncwarp();
    return patch;
}

// ===========================================================================
// Kernel: QKV projection (1-pass). z={q,k,v}.
//   q -> g_qh fp16; k -> g_kh fp16; v -> g_vth fp16 transposed [b][d][k]
// ===========================================================================
__global__ __launch_bounds__(NTHREADS, 2) void qkv_gemm(
    const float* __restrict__ bq, const float* __restrict__ bk, const float* __restrict__ bv)
{
    extern __shared__ __align__(128) char dsm[];
    const int z = blockIdx.z;
    const int m0 = blockIdx.y * 128;
    const int n0 = blockIdx.x * 128;

    float acc[4][8][4];
    gemm_mma_core(g_xh + (size_t)m0 * DIM, DIM,
                  g_wh[z] + (size_t)n0 * DIM, DIM,
                  DIM, dsm, acc);

    const int tid = threadIdx.x, wid = tid >> 5, lane = tid & 31;
    const int warpM = wid >> 1, warpN = wid & 1;
    float* patch = acc_to_patch(dsm, wid, lane, acc);
    const float* bias = (z == 0) ? bq : (z == 1) ? bk : bv;
    const int colbase = n0 + warpN * 64;
    const int mbase = m0 + warpM * 64;

    if (z < 2) {
        __half* dst = z ? g_kh : g_qh;
        const float b0 = bias[colbase + 2*lane];
        const float b1 = bias[colbase + 2*lane + 1];
        #pragma unroll 4
        for (int r = 0; r < 64; r++) {
            float v0 = patch[r * 68 + 2*lane] + b0;
            float v1 = patch[r * 68 + 2*lane + 1] + b1;
            const size_t off = (size_t)(mbase + r) * DIM + colbase + 2*lane;
            *(uint32_t*)(dst + off) = pack_h2(v0, v1);
        }
    } else {
        const int bIdx = mbase >> 11;
        const int ms = mbase & (SEQ - 1);
        #pragma unroll
        for (int half = 0; half < 2; half++) {
            const int nl = lane + half * 32;
            const int ncol = colbase + nl;
            const float bb = bias[ncol];
            __half* dst = g_vth + ((size_t)bIdx * DIM + ncol) * SEQ + ms;
            #pragma unroll
            for (int rb = 0; rb < 64; rb += 8) {
                uint32_t hp[4];
                #pragma unroll
                for (int j = 0; j < 4; j++) {
                    float v0 = patch[(rb + 2*j)     * 68 + nl] + bb;
                    float v1 = patch[(rb + 2*j + 1) * 68 + nl] + bb;
                    hp[j] = pack_h2(v0, v1);
                }
                *(uint4*)(dst + rb) = make_uint4(hp[0], hp[1], hp[2], hp[3]);
            }
        }
    }
}

// ===========================================================================
// Kernel: scores + fused exp + column-sum partials (1-pass).
//   P[b][q][k] = exp(Q.K^T / scale) fp16; zpart[b][mtile][k] partial sums.
// ===========================================================================
__global__ __launch_bounds__(NTHREADS, 2) void scores_gemm()
{
    extern __shared__ __align__(128) char dsm[];
    const int b = blockIdx.z;
    const int m0 = blockIdx.y * 128;
    const int n0 = blockIdx.x * 128;

    float acc[4][8][4];
    gemm_mma_core(g_qh + ((size_t)b * SEQ + m0) * DIM, DIM,
                  g_kh + ((size_t)b * SEQ + n0) * DIM, DIM,
                  DIM, dsm, acc);

    const int tid = threadIdx.x, wid = tid >> 5, lane = tid & 31;
    const int warpM = wid >> 1, warpN = wid & 1;
    float* patch = acc_to_patch(dsm, wid, lane, acc);
    const float inv_scale = 1.0f / (sqrtf(512.0f) + 1e-6f);
    const int colbase = n0 + warpN * 64;
    const int mbase = m0 + warpM * 64;
    __half* Ph = g_ph + (size_t)b * SEQ * SEQ;

    float az0 = 0.0f, az1 = 0.0f;
    #pragma unroll 4
    for (int r = 0; r < 64; r++) {
        float e0 = __expf(patch[r * 68 + 2*lane]     * inv_scale);
        float e1 = __expf(patch[r * 68 + 2*lane + 1] * inv_scale);
        az0 += e0; az1 += e1;
        const size_t off = (size_t)(mbase + r) * SEQ + colbase + 2*lane;
        *(uint32_t*)(Ph + off) = pack_h2(e0, e1);
    }

    // deterministic cross-warp column-sum reduction (4 warps: warpM 0,1 per warpN)
    float* zbuf = (float*)(dsm + 4 * PATCH_B);   // [4 warps][64 cols]
    zbuf[wid * 64 + 2*lane]     = az0;
    zbuf[wid * 64 + 2*lane + 1] = az1;
    __syncthreads();
    {
        const int wN = tid >> 6;       // 0..1
        const int c = tid & 63;
        // warps with warpN == wN: wid = wN (warpM=0) and 2+wN (warpM=1)
        float zsum = zbuf[wN * 64 + c] + zbuf[(2 + wN) * 64 + c];
        g_zpart[((size_t)b * 16 + blockIdx.y) * SEQ + n0 + wN * 64 + c] = zsum;
    }
}

// ===========================================================================
// Kernel: fused zinv + V scaling.
// grid (kc, dc, b) = (8, 8, 8); block 256.
// Each block: compute zinv for its 256 k-columns into smem, then scale
// V^T[b][d0..d0+64][k0..k0+256] in place.
// ===========================================================================
__global__ __launch_bounds__(256) void zscale_kernel()
{
    const int kc = blockIdx.x;
    const int dc = blockIdx.y;
    const int b  = blockIdx.z;
    const int t  = threadIdx.x;

    __shared__ float szinv[256];
    {
        const int k = kc * 256 + t;
        float zsum = 0.0f;
        #pragma unroll
        for (int j = 0; j < 16; j++)
            zsum += g_zpart[((size_t)b * 16 + j) * SEQ + k];
        szinv[t] = 1.0f / zsum;
    }
    __syncthreads();

    const int kk = (t & 31) * 8;          // 8 halfs per thread along k
    const int rowl = t >> 5;              // 8 rows per pass
    #pragma unroll
    for (int pass = 0; pass < 8; pass++) {
        const int d = dc * 64 + pass * 8 + rowl;
        const size_t base = ((size_t)b * DIM + d) * SEQ + kc * 256 + kk;
        uint4 v = *(const uint4*)(g_vth + base);
        __half2* hp = (__half2*)&v;
        const float* zi = szinv + kk;
        hp[0] = __floats2half2_rn(__low2float(hp[0]) * zi[0], __high2float(hp[0]) * zi[1]);
        hp[1] = __floats2half2_rn(__low2float(hp[1]) * zi[2], __high2float(hp[1]) * zi[3]);
        hp[2] = __floats2half2_rn(__low2float(hp[2]) * zi[4], __high2float(hp[2]) * zi[5]);
        hp[3] = __floats2half2_rn(__low2float(hp[3]) * zi[6], __high2float(hp[3]) * zi[7]);
        *(uint4*)(g_vth + base) = v;
    }
}

// ===========================================================================
// Kernel: out[b][q][d] = P @ (V/z)  (1-pass), fp32 out
// ===========================================================================
__global__ __launch_bounds__(NTHREADS, 2) void out_gemm(float* __restrict__ outp)
{
    extern __shared__ __align__(128) char dsm[];
    const int b = blockIdx.z;
    const int m0 = blockIdx.y * 128;
    const int n0 = blockIdx.x * 128;

    float acc[4][8][4];
    gemm_mma_core(g_ph + (size_t)b * SEQ * SEQ + (size_t)m0 * SEQ, SEQ,
                  g_vth + (size_t)b * DIM * SEQ + (size_t)n0 * SEQ, SEQ,
                  SEQ, dsm, acc);

    const int tid = threadIdx.x, wid = tid >> 5, lane = tid & 31;
    const int warpM = wid >> 1, warpN = wid & 1;
    float* patch = acc_to_patch(dsm, wid, lane, acc);
    float* Cp = outp + (size_t)b * SEQ * DIM;
    const int colbase = n0 + warpN * 64;
    const int mbase = m0 + warpM * 64;

    #pragma unroll 4
    for (int r = 0; r < 64; r++) {
        float2 v;
        v.x = patch[r * 68 + 2*lane];
        v.y = patch[r * 68 + 2*lane + 1];
        *(float2*)(Cp + (size_t)(mbase + r) * DIM + colbase + 2*lane) = v;
    }
}

// ===========================================================================
// Kernel: convert fp32 sources to fp16 (x, Wq, Wk, Wv), 8 elems/thread
// ===========================================================================
__global__ void split_all(const float* __restrict__ x,
                          const float* __restrict__ Wq,
                          const float* __restrict__ Wk,
                          const float* __restrict__ Wv)
{
    const size_t XN = (size_t)MROWS * DIM;
    const size_t WN = (size_t)DIM * DIM;
    size_t i = ((size_t)blockIdx.x * 256 + threadIdx.x) * 8;
    const float* src;
    __half* dh;
    size_t j;
    if (i < XN) {
        src = x; dh = g_xh; j = i;
    } else {
        size_t k = i - XN;
        if (k >= 3 * WN) return;
        int z = (int)(k / WN);
        j = k % WN;
        src = (z == 0) ? Wq : (z == 1) ? Wk : Wv;
        dh = g_wh[z];
    }
    float4 v0 = *(const float4*)(src + j);
    float4 v1 = *(const float4*)(src + j + 4);
    uint4 o;
    o.x = pack_h2(v0.x, v0.y);
    o.y = pack_h2(v0.z, v0.w);
    o.z = pack_h2(v1.x, v1.y);
    o.w = pack_h2(v1.z, v1.w);
    *(uint4*)(dh + j) = o;
}

// ===========================================================================
// Launch
// ===========================================================================
extern "C" void kernel_launch(void* const* d_in, const int* in_sizes, int n_in,
                              void* d_out, int out_size)
{
    const float* x  = (const float*)d_in[0];
    const float* Wq = (const float*)d_in[1];
    const float* bq = (const float*)d_in[2];
    const float* Wk = (const float*)d_in[3];
    const float* bk = (const float*)d_in[4];
    const float* Wv = (const float*)d_in[5];
    const float* bv = (const float*)d_in[6];
    float* outp = (float*)d_out;
    (void)in_sizes; (void)n_in; (void)out_size;

    cudaFuncSetAttribute(qkv_gemm,    cudaFuncAttributeMaxDynamicSharedMemorySize, DYN_SMEM);
    cudaFuncSetAttribute(scores_gemm, cudaFuncAttributeMaxDynamicSharedMemorySize, DYN_SMEM);
    cudaFuncSetAttribute(out_gemm,    cudaFuncAttributeMaxDynamicSharedMemorySize, DYN_SMEM);

    // 1) convert x + weights to fp16 (8 elems/thread)
    {
        size_t total = ((size_t)MROWS * DIM + 3 * (size_t)DIM * DIM) / 8;
        int blocks = (int)((total + 255) / 256);
        split_all<<<blocks, 256>>>(x, Wq, Wk, Wv);
    }
    // 2) QKV projections (V written transposed fp16)
    {
        dim3 grid(DIM / 128, MROWS / 128, 3);
        qkv_gemm<<<grid, NTHREADS, DYN_SMEM>>>(bq, bk, bv);
    }
    // 3) scores + exp + column partial sums
    {
        dim3 grid(SEQ / 128, SEQ / 128, BATCH);
        scores_gemm<<<grid, NTHREADS, DYN_SMEM>>>();
    }
    // 4) fused z inverse + V scaling (in place)
    {
        dim3 grid(SEQ / 256, DIM / 64, BATCH);
        zscale_kernel<<<grid, 256>>>();
    }
    // 5) output GEMM
    {
        dim3 grid(DIM / 128, SEQ / 128, BATCH);
        out_gemm<<<grid, NTHREADS, DYN_SMEM>>>(outp);
    }
}

// round 15
// speedup vs baseline: 1.0156x; 1.0156x over previous
#include <cuda_runtime.h>
#include <cuda_fp16.h>
#include <cstdint>
#include <math.h>

#define BATCH 8
#define SEQ   2048
#define DIM   512
#define MROWS (BATCH*SEQ)   // 16384

// ===========================================================================
// Scratch in __device__ globals (allocation-free rule)
// ===========================================================================
__device__ __align__(256) __half g_xh[(size_t)MROWS * DIM];
__device__ __align__(256) __half g_wh[3][DIM * DIM];
__device__ __align__(256) __half g_qh[(size_t)MROWS * DIM];
__device__ __align__(256) __half g_kh[(size_t)MROWS * DIM];
__device__ __align__(256) __half g_vth[(size_t)BATCH * DIM * SEQ];  // V^T [b][d][k], scaled in place by 1/z
__device__ __align__(256) __half g_ph[(size_t)BATCH * SEQ * SEQ];   // exp(S)
__device__ __align__(256) float  g_zpart[(size_t)BATCH * 16 * SEQ]; // col-sum partials

// ===========================================================================
// PTX helpers (base ISA: cp.async / ldmatrix / mma.sync fp16)
// ===========================================================================
__device__ __forceinline__ uint32_t smem_u32(const void* p) {
    uint32_t a;
    asm("{ .reg .u64 t; cvta.to.shared.u64 t, %1; cvt.u32.u64 %0, t; }" : "=r"(a) : "l"(p));
    return a;
}
__device__ __forceinline__ void cp16(uint32_t s, const void* g) {
    asm volatile("cp.async.cg.shared.global [%0], [%1], 16;" :: "r"(s), "l"(g) : "memory");
}
#define CP_COMMIT()  asm volatile("cp.async.commit_group;" ::: "memory")
#define CP_WAIT3()   asm volatile("cp.async.wait_group 3;" ::: "memory")

#define LDSM4(r0, r1, r2, r3, addr) \
    asm volatile("ldmatrix.sync.aligned.m8n8.x4.shared.b16 {%0,%1,%2,%3}, [%4];" \
                 : "=r"(r0), "=r"(r1), "=r"(r2), "=r"(r3) : "r"(addr))

#define MMA_FP16(c, a, b) \
    asm volatile("mma.sync.aligned.m16n8k16.row.col.f32.f16.f16.f32 " \
                 "{%0,%1,%2,%3}, {%4,%5,%6,%7}, {%8,%9}, {%0,%1,%2,%3};" \
                 : "+f"((c)[0]), "+f"((c)[1]), "+f"((c)[2]), "+f"((c)[3]) \
                 : "r"((a)[0]), "r"((a)[1]), "r"((a)[2]), "r"((a)[3]), \
                   "r"((b)[0]), "r"((b)[1]))

// SMEM tile geometry: 128 rows x 32 fp16 (64B), padded to 80B/row (conflict-free)
#define ROW_B       80
#define TILE_B      (128 * ROW_B)          // 10240
#define STAGE_B     (2 * TILE_B)           // 20480 (A, B)
#define NSTAGE      5
#define DYN_SMEM    (NSTAGE * STAGE_B)     // 102400

__device__ __forceinline__ uint32_t pack_h2(float a, float b) {
    __half2 h = __floats2half2_rn(a, b);
    return *(uint32_t*)&h;
}

// ===========================================================================
// cp.async one K-chunk (32 cols) of A and B tiles into a stage.
// 512 x 16B per tile; each thread does 2 per tile.
// ===========================================================================
__device__ __forceinline__ void issue_chunk(
    uint32_t sbase, const char* a, const char* b,
    int ldaB, int ldbB, int koff, int tid)
{
    #pragma unroll
    for (int i = 0; i < 2; i++) {
        const int c = tid + (i << 8);
        const int r = c >> 2;
        const int sg = (c & 3) << 4;
        const uint32_t so = (uint32_t)(r * ROW_B + sg);
        cp16(sbase + so,          a + (size_t)r * (size_t)ldaB + koff + sg);
        cp16(sbase + TILE_B + so, b + (size_t)r * (size_t)ldbB + koff + sg);
    }
}

// ===========================================================================
// Compute one K-chunk (32), single-pass fp16.
// ===========================================================================
__device__ __forceinline__ void compute_chunk(
    uint32_t sbase, int warpM, int warpN, int lane, float acc[2][8][4])
{
    const int rsel = (lane & 7) + ((lane >> 3) & 1) * 8;
    const int ksel = (lane >> 4) * 8;
    #pragma unroll
    for (int ks = 0; ks < 2; ks++) {
        const int kb = (ks * 16 + ksel) * 2;   // bytes
        uint32_t a_r[2][4];
        #pragma unroll
        for (int m = 0; m < 2; m++) {
            const uint32_t ad = sbase + (uint32_t)((warpM * 32 + m * 16 + rsel) * ROW_B + kb);
            LDSM4(a_r[m][0], a_r[m][1], a_r[m][2], a_r[m][3], ad);
        }
        uint32_t b_r[8][2];
        #pragma unroll
        for (int np = 0; np < 4; np++) {
            const uint32_t bd = sbase + TILE_B +
                (uint32_t)((warpN * 64 + np * 16 + rsel) * ROW_B + kb);
            uint32_t r0, r1, r2, r3;
            LDSM4(r0, r1, r2, r3, bd);
            b_r[2*np][0] = r0; b_r[2*np+1][0] = r1; b_r[2*np][1] = r2; b_r[2*np+1][1] = r3;
        }
        #pragma unroll
        for (int m = 0; m < 2; m++)
            #pragma unroll
            for (int n = 0; n < 8; n++)
                MMA_FP16(acc[m][n], a_r[m], b_r[n]);
    }
}

// ===========================================================================
// Full CTA GEMM core (128x128 tile, 256 threads, 8 warps 4Mx2N, 1-pass fp16)
// Single-__syncthreads mainloop (proven structure, rounds 8/11/13):
//   per iter: wait(NSTAGE-2) -> sync -> issue chunk c+NSTAGE-1 -> compute(c)
// ===========================================================================
__device__ __forceinline__ void gemm_mma_core(
    const __half* a, int lda, const __half* b, int ldb,
    int K, char* dsm, float acc[2][8][4])
{
    const int tid = threadIdx.x;
    const int lane = tid & 31;
    const int wid = tid >> 5;
    const int warpM = wid >> 1;
    const int warpN = wid & 1;
    const uint32_t sdyn = smem_u32(dsm);
    const int ldaB = lda * 2, ldbB = ldb * 2;
    const int NC = K / 32;

    #pragma unroll
    for (int m = 0; m < 2; m++)
        #pragma unroll
        for (int n = 0; n < 8; n++)
            #pragma unroll
            for (int q = 0; q < 4; q++) acc[m][n][q] = 0.0f;

    #pragma unroll
    for (int p = 0; p < NSTAGE - 1; p++) {
        issue_chunk(sdyn + (uint32_t)p * STAGE_B,
                    (const char*)a, (const char*)b, ldaB, ldbB, p * 64, tid);
        CP_COMMIT();
    }
    for (int c = 0; c < NC; c++) {
        CP_WAIT3();                       // chunk c landed (3 newest groups may pend)
        __syncthreads();                  // visibility + slot-overwrite protection
        const int cn = c + NSTAGE - 1;
        if (cn < NC)
            issue_chunk(sdyn + (uint32_t)(cn % NSTAGE) * STAGE_B,
                        (const char*)a, (const char*)b, ldaB, ldbB, cn * 64, tid);
        CP_COMMIT();
        compute_chunk(sdyn + (uint32_t)(c % NSTAGE) * STAGE_B, warpM, warpN, lane, acc);
    }
    __syncthreads();   // all warps done computing before epilogue reuses dsm
}

// Per-warp smem patch: 32 rows x 68 floats (padded)
#define PATCH_B 8704
__device__ __forceinline__ float* acc_to_patch(char* dsm, int wid, int lane,
                                               float acc[2][8][4])
{
    float* patch = (float*)(dsm + wid * PATCH_B);
    const int r = lane >> 2;
    const int q2 = (lane & 3) * 2;
    #pragma unroll
    for (int m = 0; m < 2; m++)
        #pragma unroll
        for (int n = 0; n < 8; n++) {
            const int cb = n * 8 + q2;
            patch[(m*16 + r)     * 68 + cb]     = acc[m][n][0];
            patch[(m*16 + r)     * 68 + cb + 1] = acc[m][n][1];
            patch[(m*16 + r + 8) * 68 + cb]     = acc[m][n][2];
            patch[(m*16 + r + 8) * 68 + cb + 1] = acc[m][n][3];
        }
    __syncwarp();
    return patch;
}

// ===========================================================================
// Kernel: QKV projection (1-pass). z={q,k,v}.
//   q -> g_qh fp16; k -> g_kh fp16; v -> g_vth fp16 transposed [b][d][k]
// ===========================================================================
__global__ __launch_bounds__(256, 2) void qkv_gemm(
    const float* __restrict__ bq, const float* __restrict__ bk, const float* __restrict__ bv)
{
    extern __shared__ __align__(128) char dsm[];
    const int z = blockIdx.z;
    const int m0 = blockIdx.y * 128;
    const int n0 = blockIdx.x * 128;

    float acc[2][8][4];
    gemm_mma_core(g_xh + (size_t)m0 * DIM, DIM,
                  g_wh[z] + (size_t)n0 * DIM, DIM,
                  DIM, dsm, acc);

    const int tid = threadIdx.x, wid = tid >> 5, lane = tid & 31;
    const int warpM = wid >> 1, warpN = wid & 1;
    float* patch = acc_to_patch(dsm, wid, lane, acc);
    const float* bias = (z == 0) ? bq : (z == 1) ? bk : bv;
    const int colbase = n0 + warpN * 64;
    const int mbase = m0 + warpM * 32;

    if (z < 2) {
        __half* dst = z ? g_kh : g_qh;
        const float b0 = bias[colbase + 2*lane];
        const float b1 = bias[colbase + 2*lane + 1];
        #pragma unroll 4
        for (int r = 0; r < 32; r++) {
            float v0 = patch[r * 68 + 2*lane] + b0;
            float v1 = patch[r * 68 + 2*lane + 1] + b1;
            const size_t off = (size_t)(mbase + r) * DIM + colbase + 2*lane;
            *(uint32_t*)(dst + off) = pack_h2(v0, v1);
        }
    } else {
        const int bIdx = mbase >> 11;
        const int ms = mbase & (SEQ - 1);
        #pragma unroll
        for (int half = 0; half < 2; half++) {
            const int nl = lane + half * 32;
            const int ncol = colbase + nl;
            const float bb = bias[ncol];
            __half* dst = g_vth + ((size_t)bIdx * DIM + ncol) * SEQ + ms;
            #pragma unroll
            for (int rb = 0; rb < 32; rb += 8) {
                uint32_t hp[4];
                #pragma unroll
                for (int j = 0; j < 4; j++) {
                    float v0 = patch[(rb + 2*j)     * 68 + nl] + bb;
                    float v1 = patch[(rb + 2*j + 1) * 68 + nl] + bb;
                    hp[j] = pack_h2(v0, v1);
                }
                *(uint4*)(dst + rb) = make_uint4(hp[0], hp[1], hp[2], hp[3]);
            }
        }
    }
}

// ===========================================================================
// Kernel: scores + fused exp + column-sum partials (1-pass).
//   P[b][q][k] = exp(Q.K^T / scale) fp16; zpart[b][mtile][k] partial sums.
// ===========================================================================
__global__ __launch_bounds__(256, 2) void scores_gemm()
{
    extern __shared__ __align__(128) char dsm[];
    const int b = blockIdx.z;
    const int m0 = blockIdx.y * 128;
    const int n0 = blockIdx.x * 128;

    float acc[2][8][4];
    gemm_mma_core(g_qh + ((size_t)b * SEQ + m0) * DIM, DIM,
                  g_kh + ((size_t)b * SEQ + n0) * DIM, DIM,
                  DIM, dsm, acc);

    const int tid = threadIdx.x, wid = tid >> 5, lane = tid & 31;
    const int warpM = wid >> 1, warpN = wid & 1;
    float* patch = acc_to_patch(dsm, wid, lane, acc);
    const float inv_scale = 1.0f / (sqrtf(512.0f) + 1e-6f);
    const int colbase = n0 + warpN * 64;
    const int mbase = m0 + warpM * 32;
    __half* Ph = g_ph + (size_t)b * SEQ * SEQ;

    float az0 = 0.0f, az1 = 0.0f;
    #pragma unroll 4
    for (int r = 0; r < 32; r++) {
        float e0 = __expf(patch[r * 68 + 2*lane]     * inv_scale);
        float e1 = __expf(patch[r * 68 + 2*lane + 1] * inv_scale);
        az0 += e0; az1 += e1;
        const size_t off = (size_t)(mbase + r) * SEQ + colbase + 2*lane;
        *(uint32_t*)(Ph + off) = pack_h2(e0, e1);
    }

    // deterministic cross-warp column-sum reduction
    float* zbuf = (float*)(dsm + 8 * PATCH_B);   // [8 warps][64 cols]
    zbuf[wid * 64 + 2*lane]     = az0;
    zbuf[wid * 64 + 2*lane + 1] = az1;
    __syncthreads();
    if (tid < 128) {
        const int wN = tid >> 6;
        const int c = tid & 63;
        float zsum = 0.0f;
        #pragma unroll
        for (int wm = 0; wm < 4; wm++)
            zsum += zbuf[(2*wm + wN) * 64 + c];
        g_zpart[((size_t)b * 16 + blockIdx.y) * SEQ + n0 + wN * 64 + c] = zsum;
    }
}

// ===========================================================================
// Kernel: fused zinv + V scaling (finer-grained for occupancy).
// grid (kc, dc, b) = (8, 32, 8) = 2048 blocks; block 256.
// Each block: compute zinv for its 256 k-columns into smem (redundant across
// dc, L2-cached), then scale V^T[b][16 d-rows][256 k] in place (2 passes).
// Same per-element arithmetic and sum order as before -> bit-identical.
// ===========================================================================
__global__ __launch_bounds__(256) void zscale_kernel()
{
    const int kc = blockIdx.x;
    const int dc = blockIdx.y;
    const int b  = blockIdx.z;
    const int t  = threadIdx.x;

    __shared__ float szinv[256];
    {
        const int k = kc * 256 + t;
        float zsum = 0.0f;
        #pragma unroll
        for (int j = 0; j < 16; j++)
            zsum += g_zpart[((size_t)b * 16 + j) * SEQ + k];
        szinv[t] = 1.0f / zsum;
    }
    __syncthreads();

    const int kk = (t & 31) * 8;          // 8 halfs per thread along k
    const int rowl = t >> 5;              // 8 rows per pass
    #pragma unroll
    for (int pass = 0; pass < 2; pass++) {
        const int d = dc * 16 + pass * 8 + rowl;
        const size_t base = ((size_t)b * DIM + d) * SEQ + kc * 256 + kk;
        uint4 v = *(const uint4*)(g_vth + base);
        __half2* hp = (__half2*)&v;
        const float* zi = szinv + kk;
        hp[0] = __floats2half2_rn(__low2float(hp[0]) * zi[0], __high2float(hp[0]) * zi[1]);
        hp[1] = __floats2half2_rn(__low2float(hp[1]) * zi[2], __high2float(hp[1]) * zi[3]);
        hp[2] = __floats2half2_rn(__low2float(hp[2]) * zi[4], __high2float(hp[2]) * zi[5]);
        hp[3] = __floats2half2_rn(__low2float(hp[3]) * zi[6], __high2float(hp[3]) * zi[7]);
        *(uint4*)(g_vth + base) = v;
    }
}

// ===========================================================================
// Kernel: out[b][q][d] = P @ (V/z)  (1-pass), fp32 out
// ===========================================================================
__global__ __launch_bounds__(256, 2) void out_gemm(float* __restrict__ outp)
{
    extern __shared__ __align__(128) char dsm[];
    const int b = blockIdx.z;
    const int m0 = blockIdx.y * 128;
    const int n0 = blockIdx.x * 128;

    float acc[2][8][4];
    gemm_mma_core(g_ph + (size_t)b * SEQ * SEQ + (size_t)m0 * SEQ, SEQ,
                  g_vth + (size_t)b * DIM * SEQ + (size_t)n0 * SEQ, SEQ,
                  SEQ, dsm, acc);

    const int tid = threadIdx.x, wid = tid >> 5, lane = tid & 31;
    const int warpM = wid >> 1, warpN = wid & 1;
    float* patch = acc_to_patch(dsm, wid, lane, acc);
    float* Cp = outp + (size_t)b * SEQ * DIM;
    const int colbase = n0 + warpN * 64;
    const int mbase = m0 + warpM * 32;

    #pragma unroll 4
    for (int r = 0; r < 32; r++) {
        float2 v;
        v.x = patch[r * 68 + 2*lane];
        v.y = patch[r * 68 + 2*lane + 1];
        *(float2*)(Cp + (size_t)(mbase + r) * DIM + colbase + 2*lane) = v;
    }
}

// ===========================================================================
// Kernel: convert fp32 sources to fp16 (x, Wq, Wk, Wv), 8 elems/thread
// ===========================================================================
__global__ void split_all(const float* __restrict__ x,
                          const float* __restrict__ Wq,
                          const float* __restrict__ Wk,
                          const float* __restrict__ Wv)
{
    const size_t XN = (size_t)MROWS * DIM;
    const size_t WN = (size_t)DIM * DIM;
    size_t i = ((size_t)blockIdx.x * 256 + threadIdx.x) * 8;
    const float* src;
    __half* dh;
    size_t j;
    if (i < XN) {
        src = x; dh = g_xh; j = i;
    } else {
        size_t k = i - XN;
        if (k >= 3 * WN) return;
        int z = (int)(k / WN);
        j = k % WN;
        src = (z == 0) ? Wq : (z == 1) ? Wk : Wv;
        dh = g_wh[z];
    }
    float4 v0 = *(const float4*)(src + j);
    float4 v1 = *(const float4*)(src + j + 4);
    uint4 o;
    o.x = pack_h2(v0.x, v0.y);
    o.y = pack_h2(v0.z, v0.w);
    o.z = pack_h2(v1.x, v1.y);
    o.w = pack_h2(v1.z, v1.w);
    *(uint4*)(dh + j) = o;
}

// ===========================================================================
// Launch
// ===========================================================================
extern "C" void kernel_launch(void* const* d_in, const int* in_sizes, int n_in,
                              void* d_out, int out_size)
{
    const float* x  = (const float*)d_in[0];
    const float* Wq = (const float*)d_in[1];
    const float* bq = (const float*)d_in[2];
    const float* Wk = (const float*)d_in[3];
    const float* bk = (const float*)d_in[4];
    const float* Wv = (const float*)d_in[5];
    const float* bv = (const float*)d_in[6];
    float* outp = (float*)d_out;
    (void)in_sizes; (void)n_in; (void)out_size;

    cudaFuncSetAttribute(qkv_gemm,    cudaFuncAttributeMaxDynamicSharedMemorySize, DYN_SMEM);
    cudaFuncSetAttribute(scores_gemm, cudaFuncAttributeMaxDynamicSharedMemorySize, DYN_SMEM);
    cudaFuncSetAttribute(out_gemm,    cudaFuncAttributeMaxDynamicSharedMemorySize, DYN_SMEM);

    // 1) convert x + weights to fp16 (8 elems/thread)
    {
        size_t total = ((size_t)MROWS * DIM + 3 * (size_t)DIM * DIM) / 8;
        int blocks = (int)((total + 255) / 256);
        split_all<<<blocks, 256>>>(x, Wq, Wk, Wv);
    }
    // 2) QKV projections (V written transposed fp16)
    {
        dim3 grid(DIM / 128, MROWS / 128, 3);
        qkv_gemm<<<grid, 256, DYN_SMEM>>>(bq, bk, bv);
    }
    // 3) scores + exp + column partial sums
    {
        dim3 grid(SEQ / 128, SEQ / 128, BATCH);
        scores_gemm<<<grid, 256, DYN_SMEM>>>();
    }
    // 4) fused z inverse + V scaling (in place, fine-grained)
    {
        dim3 grid(SEQ / 256, DIM / 16, BATCH);
        zscale_kernel<<<grid, 256>>>();
    }
    // 5) output GEMM
    {
        dim3 grid(DIM / 128, SEQ / 128, BATCH);
        out_gemm<<<grid, 256, DYN_SMEM>>>(outp);
    }
}